// round 13
// baseline (speedup 1.0000x reference)
#include <cuda_runtime.h>
#include <cuda_fp16.h>
#include <cstdint>
#include <cstddef>

// R13: HYBRID pipe LSTM, anti-phased.
// vs R12: (1) warps 0-3 tensor-first, warps 4-7 fma-first (SMSP k hosts warps
// {k,k+4} -> each SMSP always has one warp feeding HMMA and one issuing
// HFMA2; R12's in-phase warps serialized the two pipes); (2) fma side loads
// via LDS.128 (16 per block) instead of 64x LDS.32.
// GEMM split: HMMA k 64..127 + 256..383; HFMA2 k 0..63 + 128..255.
// 128 CTAs = 8 M-groups(64 rows) x 16 N-tiles(16 jl x 4 gates).

#define SEQ   512
#define BATCH 512
#define DIM   128
#define HID   256
#define G4    1024
#define NCTA  128
#define NTHR  256
#define NGRP  16

#define SA_BYTES  49152            // A tile: 24 ks x 2048B
#define WF_OFF    SA_BYTES
#define WF_STRIDE 400              // bytes per col (96 pairs*4 + 16 pad), 16|400
#define WF_BYTES  (64 * WF_STRIDE) // 25600
#define SMEM_TOTAL (SA_BYTES + WF_BYTES)

// ---- persistent device scratch ----
__device__ __align__(16) __half g_h16[2][BATCH * HID];
__device__ __align__(128) unsigned long long g_bar_grp[8][16];

__device__ __forceinline__ uint32_t smem_u32(const void* p) {
    uint32_t a;
    asm("{ .reg .u64 t; cvta.to.shared.u64 t, %1; cvt.u32.u64 %0, t; }"
        : "=r"(a) : "l"(p));
    return a;
}
__device__ __forceinline__ void ldsm4(uint32_t a[4], uint32_t addr) {
    asm volatile("ldmatrix.sync.aligned.m8n8.x4.shared.b16 {%0,%1,%2,%3}, [%4];"
                 : "=r"(a[0]), "=r"(a[1]), "=r"(a[2]), "=r"(a[3]) : "r"(addr));
}
__device__ __forceinline__ void mma_f16acc(uint32_t c[2], const uint32_t a[4],
                                           uint32_t b0, uint32_t b1) {
    asm volatile(
        "mma.sync.aligned.m16n8k16.row.col.f16.f16.f16.f16 "
        "{%0,%1}, {%2,%3,%4,%5}, {%6,%7}, {%0,%1};"
        : "+r"(c[0]), "+r"(c[1])
        : "r"(a[0]), "r"(a[1]), "r"(a[2]), "r"(a[3]), "r"(b0), "r"(b1));
}
__device__ __forceinline__ void promote(float acc[4], uint32_t hc[2]) {
    float2 lo = __half22float2(*reinterpret_cast<__half2*>(&hc[0]));
    float2 hi = __half22float2(*reinterpret_cast<__half2*>(&hc[1]));
    acc[0] += lo.x; acc[1] += lo.y; acc[2] += hi.x; acc[3] += hi.y;
    hc[0] = 0u; hc[1] = 0u;
}
__device__ __forceinline__ float tanh_mufu(float x) {
    float y;
    asm("tanh.approx.f32 %0, %1;" : "=f"(y) : "f"(x));
    return y;
}
__device__ __forceinline__ float sig_mufu(float x) {
    return fmaf(0.5f, tanh_mufu(0.5f * x), 0.5f);
}
__device__ __forceinline__ uint32_t a_phys(int ks, int row, int kh) {
    return (uint32_t)(ks * 2048 + row * 32 + ((kh << 4) ^ ((row & 4) << 2)));
}
__device__ __forceinline__ __half2 h2_of(uint32_t u) {
    union { uint32_t u; __half2 h; } c; c.u = u; return c.h;
}

__global__ void __launch_bounds__(NTHR, 1)
lstm_hyb(const float* __restrict__ x,  const float* __restrict__ Wx,
         const float* __restrict__ Wh, const float* __restrict__ bv,
         const float* __restrict__ Wd, const float* __restrict__ bd,
         float* __restrict__ out)
{
    extern __shared__ __align__(1024) char smem[];
    char* sA  = smem;
    char* sWf = smem + WF_OFF;
    const uint32_t sA_u = smem_u32(sA);

    const int tid  = threadIdx.x;
    const int cta  = blockIdx.x;
    const int warp = tid >> 5, lane = tid & 31;
    const int grp = cta >> 4;
    const int r0 = grp * 64;
    const int j0 = (cta & 15) * 16;
    const int wM = warp & 1;            // 2-way M split (32 rows)
    const int wN = warp >> 1;           // 4-way N split (16 n-cols)
    const int ph = warp >> 2;           // phase: 0 = tensor-first, 1 = fma-first
    unsigned long long* const bar_ctr = &g_bar_grp[grp][0];

    // ---- one-time: tensor-side B fragments (12 ks) into registers ----
    // bi 0..3 -> ks 4..7 (x k 64..127); bi 4..11 -> ks 16..23 (h k 256..383)
    uint32_t bfr[12][2][2];
    #pragma unroll
    for (int bi = 0; bi < 12; ++bi) {
        int ksg = (bi < 4) ? (4 + bi) : (16 + (bi - 4));
        #pragma unroll
        for (int nb = 0; nb < 2; ++nb) {
            int n = wN * 16 + nb * 8 + (lane >> 2);
            int col = (n & 3) * HID + j0 + (n >> 2);
            int k0 = ksg * 16 + (lane & 3) * 2;
            float w0, w1, w2, w3;
            if (k0 < DIM) {
                w0 = Wx[(size_t)k0 * G4 + col];
                w1 = Wx[(size_t)(k0 + 1) * G4 + col];
                w2 = Wx[(size_t)(k0 + 8) * G4 + col];
                w3 = Wx[(size_t)(k0 + 9) * G4 + col];
            } else {
                w0 = Wh[(size_t)(k0 - DIM) * G4 + col];
                w1 = Wh[(size_t)(k0 - DIM + 1) * G4 + col];
                w2 = Wh[(size_t)(k0 - DIM + 8) * G4 + col];
                w3 = Wh[(size_t)(k0 - DIM + 9) * G4 + col];
            }
            union { __half2 h; uint32_t u; } p0, p1;
            p0.h = __floats2half2_rn(w0, w1);
            p1.h = __floats2half2_rn(w2, w3);
            bfr[bi][nb][0] = p0.u;
            bfr[bi][nb][1] = p1.u;
        }
    }

    // ---- one-time: fma-side weights into sWf [col][pair] fp16 ----
    // kf 0..63 -> k=kf (x); kf 64..191 -> k=64+kf (h k 128..255)
    for (int idx = tid; idx < 64 * 192; idx += NTHR) {
        int kf = idx >> 6, n = idx & 63;
        int k = (kf < 64) ? kf : (64 + kf);
        int col = (n & 3) * HID + j0 + (n >> 2);
        float w = (k < DIM) ? Wx[(size_t)k * G4 + col]
                            : Wh[(size_t)(k - DIM) * G4 + col];
        *(__half*)(sWf + n * WF_STRIDE + (kf >> 1) * 4 + (kf & 1) * 2) =
            __float2half_rn(w);
    }

    // zero h buffer 0
    ((uint2*)g_h16[0])[cta * NTHR + tid] = make_uint2(0u, 0u);

    // epilogue geometry (R8)
    const int q = lane & 3;
    const int myOdd = lane & 1;
    const int rA = wM * 32 + myOdd * 16 + (lane >> 2);
    float bI[2], bF[2], bG[2], bO[2];
    #pragma unroll
    for (int nb = 0; nb < 2; ++nb) {
        int j = j0 + wN * 4 + nb * 2 + (q >> 1);
        bI[nb] = bv[j];
        bF[nb] = bv[HID + j];
        bG[nb] = bv[2 * HID + j];
        bO[nb] = bv[3 * HID + j];
    }
    float cst[4] = {0.f, 0.f, 0.f, 0.f};

    // fma-side per-thread coords: 4 rows x 4 cols matching MMA fragments
    int Rr[4], cloc[4];
    #pragma unroll
    for (int rj = 0; rj < 4; ++rj) Rr[rj] = wM * 32 + (lane >> 2) + rj * 8;
    cloc[0] = wN * 16 + 2 * q;     cloc[1] = cloc[0] + 1;
    cloc[2] = wN * 16 + 8 + 2 * q; cloc[3] = cloc[2] + 1;

    // loader coords (R8)
    const int xrow = tid >> 2, xkb = (tid & 3) * 32;
    const int hkb  = (tid & 3) * 64;

    const int lrow = lane & 15, lkh = lane >> 4;
    uint32_t lds0 = sA_u + a_phys(0, wM * 32 + lrow, lkh);
    uint32_t lds1 = sA_u + a_phys(0, wM * 32 + 16 + lrow, lkh);

    // ---- prologue: stage x(0) ----
    {
        const float* xp = x + ((size_t)(r0 + xrow) * SEQ + 0) * DIM + xkb;
        #pragma unroll
        for (int c2 = 0; c2 < 4; ++c2) {
            float4 v0 = *(const float4*)(xp + c2 * 8);
            float4 v1 = *(const float4*)(xp + c2 * 8 + 4);
            union { __half2 h; uint32_t u; } q0, q1, q2, q3;
            q0.h = __floats2half2_rn(v0.x, v0.y);
            q1.h = __floats2half2_rn(v0.z, v0.w);
            q2.h = __floats2half2_rn(v1.x, v1.y);
            q3.h = __floats2half2_rn(v1.z, v1.w);
            int k = xkb + c2 * 8;
            *(uint4*)(sA + a_phys(k >> 4, xrow, (k >> 3) & 1)) =
                make_uint4(q0.u, q1.u, q2.u, q3.u);
        }
    }

    // full group barrier once
    {
        __syncthreads();
        if (tid == 0) {
            __threadfence();
            unsigned long long t = atomicAdd(bar_ctr, 1ULL) + 1ULL;
            unsigned long long target =
                ((t + (unsigned long long)NGRP - 1ULL) / NGRP) *
                (unsigned long long)NGRP;
            unsigned long long v;
            do {
                asm volatile("ld.acquire.gpu.u64 %0, [%1];"
                             : "=l"(v) : "l"(bar_ctr) : "memory");
            } while (v < target);
        }
        __syncthreads();
    }

    const __half2 hz = __floats2half2_rn(0.f, 0.f);

    for (int s = 0; s < SEQ; ++s) {
        // h loads first (L1-bypass); hide under x-region compute.
        const __half* hp = g_h16[s & 1];
        const uint4* hsrc = (const uint4*)(hp + (size_t)(r0 + xrow) * HID + hkb);
        uint4 hr[8];
        #pragma unroll
        for (int c = 0; c < 8; ++c) hr[c] = __ldcv(hsrc + c);

        float acc[2][2][4];
        uint32_t hc[2][2][2];
        __half2 d2[4][4];
        #pragma unroll
        for (int mb = 0; mb < 2; ++mb)
            #pragma unroll
            for (int nb = 0; nb < 2; ++nb) {
                #pragma unroll
                for (int k = 0; k < 4; ++k) acc[mb][nb][k] = 0.f;
                hc[mb][nb][0] = 0u; hc[mb][nb][1] = 0u;
            }
        #pragma unroll
        for (int rj = 0; rj < 4; ++rj)
            #pragma unroll
            for (int cj = 0; cj < 4; ++cj) d2[rj][cj] = hz;

        auto tensor_ks = [&](int ks, int bi) {
            uint32_t am0[4], am1[4];
            ldsm4(am0, lds0 + ks * 2048);
            ldsm4(am1, lds1 + ks * 2048);
            mma_f16acc(hc[0][0], am0, bfr[bi][0][0], bfr[bi][0][1]);
            mma_f16acc(hc[0][1], am0, bfr[bi][1][0], bfr[bi][1][1]);
            mma_f16acc(hc[1][0], am1, bfr[bi][0][0], bfr[bi][0][1]);
            mma_f16acc(hc[1][1], am1, bfr[bi][1][0], bfr[bi][1][1]);
        };
        // one ks block of fma work, vectorized: 16 LDS.128 + 128 HFMA2
        auto fma_blk = [&](int ksA, int pwBase) {
            #pragma unroll
            for (int kh = 0; kh < 2; ++kh) {
                uint4 av[4], wv[4];
                #pragma unroll
                for (int rj = 0; rj < 4; ++rj)
                    av[rj] = *(const uint4*)(sA + ksA * 2048 + Rr[rj] * 32 +
                              ((kh << 4) ^ ((Rr[rj] & 4) << 2)));
                #pragma unroll
                for (int cj = 0; cj < 4; ++cj)
                    wv[cj] = *(const uint4*)(sWf + cloc[cj] * WF_STRIDE +
                                             (pwBase + kh * 4) * 4);
                #pragma unroll
                for (int rj = 0; rj < 4; ++rj)
                    #pragma unroll
                    for (int cj = 0; cj < 4; ++cj) {
                        d2[rj][cj] = __hfma2(h2_of(av[rj].x), h2_of(wv[cj].x), d2[rj][cj]);
                        d2[rj][cj] = __hfma2(h2_of(av[rj].y), h2_of(wv[cj].y), d2[rj][cj]);
                        d2[rj][cj] = __hfma2(h2_of(av[rj].z), h2_of(wv[cj].z), d2[rj][cj]);
                        d2[rj][cj] = __hfma2(h2_of(av[rj].w), h2_of(wv[cj].w), d2[rj][cj]);
                    }
            }
        };
        auto promote_d2 = [&]() {
            #pragma unroll
            for (int rj = 0; rj < 4; ++rj)
                #pragma unroll
                for (int cj = 0; cj < 4; ++cj) {
                    acc[rj >> 1][cj >> 1][((rj & 1) << 1) | (cj & 1)] +=
                        __low2float(d2[rj][cj]) + __high2float(d2[rj][cj]);
                    d2[rj][cj] = hz;
                }
        };
        auto promote_all = [&]() {
            promote(acc[0][0], hc[0][0]); promote(acc[0][1], hc[0][1]);
            promote(acc[1][0], hc[1][0]); promote(acc[1][1], hc[1][1]);
            promote_d2();
        };

        // ============ x region: tensor ks 4..7 / fma blocks 0..3 ============
        if (ph == 0) {
            #pragma unroll
            for (int g = 0; g < 4; ++g) tensor_ks(4 + g, g);
            #pragma unroll
            for (int g = 0; g < 4; ++g) fma_blk(g, g * 8);
        } else {
            #pragma unroll
            for (int g = 0; g < 4; ++g) fma_blk(g, g * 8);
            #pragma unroll
            for (int g = 0; g < 4; ++g) tensor_ks(4 + g, g);
        }
        promote_all();

        // -- stage h (full 64 halfs per thread)
        #pragma unroll
        for (int c = 0; c < 8; ++c) {
            int kg = DIM + hkb + c * 8;
            *(uint4*)(sA + a_phys(kg >> 4, xrow, (kg >> 3) & 1)) = hr[c];
        }
        __syncthreads();

        // ============ h region: tensor ks 16..23 / fma blocks 8..15 ========
        if (ph == 0) {
            #pragma unroll
            for (int g = 0; g < 4; ++g) tensor_ks(16 + g, 4 + g);
            #pragma unroll
            for (int g = 0; g < 4; ++g) fma_blk(8 + g, 32 + g * 8);
            promote_all();
            #pragma unroll
            for (int g = 4; g < 8; ++g) tensor_ks(16 + g, 4 + g);
            #pragma unroll
            for (int g = 4; g < 8; ++g) fma_blk(8 + g, 32 + g * 8);
            promote_all();
        } else {
            #pragma unroll
            for (int g = 0; g < 4; ++g) fma_blk(8 + g, 32 + g * 8);
            #pragma unroll
            for (int g = 0; g < 4; ++g) tensor_ks(16 + g, 4 + g);
            promote_all();
            #pragma unroll
            for (int g = 4; g < 8; ++g) fma_blk(8 + g, 32 + g * 8);
            #pragma unroll
            for (int g = 4; g < 8; ++g) tensor_ks(16 + g, 4 + g);
            promote_all();
        }

        // -- gate exchange (R8)
        float zif[2][4], zgo[2][4];
        #pragma unroll
        for (int nb = 0; nb < 2; ++nb)
            #pragma unroll
            for (int k = 0; k < 4; ++k) {
                float s0 = __shfl_xor_sync(0xffffffffu, acc[0][nb][k], 1);
                float s1 = __shfl_xor_sync(0xffffffffu, acc[1][nb][k], 1);
                zif[nb][k] = myOdd ? s1 : acc[0][nb][k];
                zgo[nb][k] = myOdd ? acc[1][nb][k] : s0;
            }

        __half* hn = g_h16[(s + 1) & 1];
        #pragma unroll
        for (int nb = 0; nb < 2; ++nb) {
            int j = j0 + wN * 4 + nb * 2 + (q >> 1);
            float i0 = sig_mufu(zif[nb][0] + bI[nb]);
            float f0 = sig_mufu(zif[nb][1] + bF[nb]);
            float g0 = tanh_mufu(zgo[nb][0] + bG[nb]);
            float o0 = sig_mufu(zgo[nb][1] + bO[nb]);
            float i1 = sig_mufu(zif[nb][2] + bI[nb]);
            float f1 = sig_mufu(zif[nb][3] + bF[nb]);
            float g1 = tanh_mufu(zgo[nb][2] + bG[nb]);
            float o1 = sig_mufu(zgo[nb][3] + bO[nb]);
            cst[nb * 2 + 0] = f0 * cst[nb * 2 + 0] + i0 * g0;
            cst[nb * 2 + 1] = f1 * cst[nb * 2 + 1] + i1 * g1;
            hn[(size_t)(r0 + rA) * HID + j] =
                __float2half_rn(o0 * tanh_mufu(cst[nb * 2 + 0]));
            hn[(size_t)(r0 + rA + 8) * HID + j] =
                __float2half_rn(o1 * tanh_mufu(cst[nb * 2 + 1]));
        }

        // -- split barrier: arrive, stage x(s+1) in the window, wait
        __syncthreads();
        unsigned long long tick = 0;
        if (tid == 0) {
            asm volatile("atom.add.release.gpu.global.u64 %0, [%1], 1;"
                         : "=l"(tick) : "l"(bar_ctr) : "memory");
            tick += 1ULL;
        }
        if (s + 1 < SEQ) {
            const float* xp = x + ((size_t)(r0 + xrow) * SEQ + (s + 1)) * DIM + xkb;
            #pragma unroll
            for (int c2 = 0; c2 < 4; ++c2) {
                float4 v0 = *(const float4*)(xp + c2 * 8);
                float4 v1 = *(const float4*)(xp + c2 * 8 + 4);
                union { __half2 h; uint32_t u; } q0, q1, q2, q3;
                q0.h = __floats2half2_rn(v0.x, v0.y);
                q1.h = __floats2half2_rn(v0.z, v0.w);
                q2.h = __floats2half2_rn(v1.x, v1.y);
                q3.h = __floats2half2_rn(v1.z, v1.w);
                int k = xkb + c2 * 8;
                *(uint4*)(sA + a_phys(k >> 4, xrow, (k >> 3) & 1)) =
                    make_uint4(q0.u, q1.u, q2.u, q3.u);
            }
        }
        if (tid == 0) {
            unsigned long long target =
                ((tick + (unsigned long long)NGRP - 1ULL) / NGRP) *
                (unsigned long long)NGRP;
            unsigned long long v;
            do {
                asm volatile("ld.acquire.gpu.u64 %0, [%1];"
                             : "=l"(v) : "l"(bar_ctr) : "memory");
            } while (v < target);
        }
        __syncthreads();
    }

    // ---- classifier + softmax (R8) ----
    if (warp < 4) {
        const int row = cta * 4 + warp;
        const __half* hf = g_h16[0];
        float acc10[10];
        #pragma unroll
        for (int c = 0; c < 10; ++c) acc10[c] = 0.f;
        uint4 hv = __ldcv((const uint4*)(hf + (size_t)row * HID + lane * 8));
        const __half* hvh = (const __half*)&hv;
        #pragma unroll
        for (int u = 0; u < 8; ++u) {
            float h = __half2float(hvh[u]);
            const float* wd = Wd + (size_t)(lane * 8 + u) * 10;
            #pragma unroll
            for (int c = 0; c < 10; ++c) acc10[c] += h * wd[c];
        }
        #pragma unroll
        for (int off = 16; off > 0; off >>= 1) {
            #pragma unroll
            for (int c = 0; c < 10; ++c)
                acc10[c] += __shfl_down_sync(0xffffffffu, acc10[c], off);
        }
        if (lane == 0) {
            float m = -3.0e38f;
            #pragma unroll
            for (int c = 0; c < 10; ++c) { acc10[c] += bd[c]; m = fmaxf(m, acc10[c]); }
            float ssum = 0.f;
            #pragma unroll
            for (int c = 0; c < 10; ++c) { acc10[c] = __expf(acc10[c] - m); ssum += acc10[c]; }
            float inv = 1.0f / ssum;
            #pragma unroll
            for (int c = 0; c < 10; ++c) out[(size_t)row * 10 + c] = acc10[c] * inv;
        }
    }
}

extern "C" void kernel_launch(void* const* d_in, const int* in_sizes, int n_in,
                              void* d_out, int out_size) {
    const float* x  = (const float*)d_in[0];
    const float* Wx = (const float*)d_in[1];
    const float* Wh = (const float*)d_in[2];
    const float* b  = (const float*)d_in[3];
    const float* Wd = (const float*)d_in[4];
    const float* bd = (const float*)d_in[5];
    (void)in_sizes; (void)n_in; (void)out_size;
    cudaFuncSetAttribute(lstm_hyb, cudaFuncAttributeMaxDynamicSharedMemorySize,
                         SMEM_TOTAL);
    lstm_hyb<<<NCTA, NTHR, SMEM_TOTAL>>>(x, Wx, Wh, b, Wd, bd, (float*)d_out);
}

// round 14
// speedup vs baseline: 1.4771x; 1.4771x over previous
#include <cuda_runtime.h>
#include <cuda_fp16.h>
#include <cstdint>
#include <cstddef>

// R14: HMMA (x-part, fp16) + dp4a int8 (h-part) persistent LSTM.
// Theory: legacy mma.sync on sm_103a is serviced by the fp16-FMA hardware
// (R8 = 100% of that roofline; HFMA2 hybrids R10-13 failed = same pipe).
// dp4a is integer-pipe: 4 MACs/lane/issue, int32 exact accumulation.
// h is quantized to int8 by its producer (h in (-1,1)); Wh per-column int8.
// 128 CTAs = 8 M-groups(64 rows) x 16 N-tiles(16 jl x 4 gates), 256 thr.

#define SEQ   512
#define BATCH 512
#define DIM   128
#define HID   256
#define G4    1024
#define NCTA  128
#define NTHR  256
#define NGRP  16

#define SA_BYTES  16384            // x tile: 8 ks x 2048B fp16
#define ROWP      272              // int8 row pitch (16-mult, odd 16B count)
#define SQ_OFF    SA_BYTES
#define SQ_BYTES  (64 * ROWP)      // 17408: h int8 [row][256]
#define SW_OFF    (SQ_OFF + SQ_BYTES)
#define SW_BYTES  (64 * ROWP)      // 17408: Wh int8 [n][256]
#define SCS_OFF   (SW_OFF + SW_BYTES)
#define SMEM_TOTAL (SCS_OFF + 256) // + 64 col scales (float)

// ---- persistent device scratch ----
__device__ __align__(16) __half g_hfin[BATCH * HID];          // final h only
__device__ __align__(16) signed char g_hq[2][BATCH * HID];    // int8 h state
__device__ __align__(128) unsigned long long g_bar_grp[8][16];

__device__ __forceinline__ uint32_t smem_u32(const void* p) {
    uint32_t a;
    asm("{ .reg .u64 t; cvta.to.shared.u64 t, %1; cvt.u32.u64 %0, t; }"
        : "=r"(a) : "l"(p));
    return a;
}
__device__ __forceinline__ void ldsm4(uint32_t a[4], uint32_t addr) {
    asm volatile("ldmatrix.sync.aligned.m8n8.x4.shared.b16 {%0,%1,%2,%3}, [%4];"
                 : "=r"(a[0]), "=r"(a[1]), "=r"(a[2]), "=r"(a[3]) : "r"(addr));
}
__device__ __forceinline__ void mma_f16acc(uint32_t c[2], const uint32_t a[4],
                                           uint32_t b0, uint32_t b1) {
    asm volatile(
        "mma.sync.aligned.m16n8k16.row.col.f16.f16.f16.f16 "
        "{%0,%1}, {%2,%3,%4,%5}, {%6,%7}, {%0,%1};"
        : "+r"(c[0]), "+r"(c[1])
        : "r"(a[0]), "r"(a[1]), "r"(a[2]), "r"(a[3]), "r"(b0), "r"(b1));
}
__device__ __forceinline__ void promote(float acc[4], uint32_t hc[2]) {
    float2 lo = __half22float2(*reinterpret_cast<__half2*>(&hc[0]));
    float2 hi = __half22float2(*reinterpret_cast<__half2*>(&hc[1]));
    acc[0] += lo.x; acc[1] += lo.y; acc[2] += hi.x; acc[3] += hi.y;
    hc[0] = 0u; hc[1] = 0u;
}
__device__ __forceinline__ float tanh_mufu(float x) {
    float y;
    asm("tanh.approx.f32 %0, %1;" : "=f"(y) : "f"(x));
    return y;
}
__device__ __forceinline__ float sig_mufu(float x) {
    return fmaf(0.5f, tanh_mufu(0.5f * x), 0.5f);
}
__device__ __forceinline__ uint32_t a_phys(int ks, int row, int kh) {
    return (uint32_t)(ks * 2048 + row * 32 + ((kh << 4) ^ ((row & 4) << 2)));
}

__global__ void __launch_bounds__(NTHR, 1)
lstm_i8(const float* __restrict__ x,  const float* __restrict__ Wx,
        const float* __restrict__ Wh, const float* __restrict__ bv,
        const float* __restrict__ Wd, const float* __restrict__ bd,
        float* __restrict__ out)
{
    extern __shared__ __align__(1024) char smem[];
    char* sA = smem;                       // fp16 x tile (swizzled, 8 ks)
    char* sQ = smem + SQ_OFF;              // int8 h rows [64][256] pitch 272
    char* sW = smem + SW_OFF;              // int8 Wh [n=64][256] pitch 272
    float* scs = (float*)(smem + SCS_OFF); // 64 column scales
    const uint32_t sA_u = smem_u32(sA);

    const int tid  = threadIdx.x;
    const int cta  = blockIdx.x;
    const int warp = tid >> 5, lane = tid & 31;
    const int grp = cta >> 4;
    const int r0 = grp * 64;
    const int j0 = (cta & 15) * 16;
    const int wM = warp & 1;               // 2-way M split (32 rows)
    const int wN = warp >> 1;              // 4-way N split (16 n-cols)
    unsigned long long* const bar_ctr = &g_bar_grp[grp][0];

    // ---- one-time: x-side B fragments (8 ks, all Wx) into registers ----
    uint32_t bfr[8][2][2];
    #pragma unroll
    for (int bi = 0; bi < 8; ++bi) {
        #pragma unroll
        for (int nb = 0; nb < 2; ++nb) {
            int n = wN * 16 + nb * 8 + (lane >> 2);
            int col = (n & 3) * HID + j0 + (n >> 2);
            int k0 = bi * 16 + (lane & 3) * 2;
            float w0 = Wx[(size_t)k0 * G4 + col];
            float w1 = Wx[(size_t)(k0 + 1) * G4 + col];
            float w2 = Wx[(size_t)(k0 + 8) * G4 + col];
            float w3 = Wx[(size_t)(k0 + 9) * G4 + col];
            union { __half2 h; uint32_t u; } p0, p1;
            p0.h = __floats2half2_rn(w0, w1);
            p1.h = __floats2half2_rn(w2, w3);
            bfr[bi][nb][0] = p0.u;
            bfr[bi][nb][1] = p1.u;
        }
    }

    // ---- one-time: per-column scales + int8 quantized Wh into sW ----
    if (tid < 64) {
        int n = tid;
        int col = (n & 3) * HID + j0 + (n >> 2);
        float m = 1e-20f;
        for (int k = 0; k < HID; ++k)
            m = fmaxf(m, fabsf(Wh[(size_t)k * G4 + col]));
        scs[n] = m * (1.0f / 127.0f);
    }
    __syncthreads();
    for (int idx = tid; idx < 64 * HID; idx += NTHR) {
        int n = idx >> 8, k = idx & 255;
        int col = (n & 3) * HID + j0 + (n >> 2);
        float w = Wh[(size_t)k * G4 + col];
        int wq = __float2int_rn(w / scs[n]);
        wq = max(-127, min(127, wq));
        sW[n * ROWP + k] = (signed char)wq;
    }

    // zero int8 h buffer 0 (32768 threads x 4B = 128KB, group-local slices)
    ((uint32_t*)g_hq[0])[cta * NTHR + tid] = 0u;

    // epilogue geometry (R8/R12, numerically validated)
    const int q = lane & 3;
    const int myOdd = lane & 1;
    const int rA = wM * 32 + myOdd * 16 + (lane >> 2);
    float bI[2], bF[2], bG[2], bO[2];
    #pragma unroll
    for (int nb = 0; nb < 2; ++nb) {
        int j = j0 + wN * 4 + nb * 2 + (q >> 1);
        bI[nb] = bv[j];
        bF[nb] = bv[HID + j];
        bG[nb] = bv[2 * HID + j];
        bO[nb] = bv[3 * HID + j];
    }
    float cst[4] = {0.f, 0.f, 0.f, 0.f};

    // dp4a-side coords (R12 mapping): 4 rows x 4 cols per thread
    int Rr[4], cloc[4];
    #pragma unroll
    for (int rj = 0; rj < 4; ++rj) Rr[rj] = wM * 32 + (lane >> 2) + rj * 8;
    cloc[0] = wN * 16 + 2 * q;     cloc[1] = cloc[0] + 1;
    cloc[2] = wN * 16 + 8 + 2 * q; cloc[3] = cloc[2] + 1;
    __syncthreads();
    float scW[4];
    #pragma unroll
    for (int cj = 0; cj < 4; ++cj) scW[cj] = scs[cloc[cj]] * (1.0f / 127.0f);

    // loader coords
    const int xrow = tid >> 2, xkb = (tid & 3) * 32;   // x: 32 floats/thread
    const int qt   = tid & 3;                          // hq quarter (64 int8)

    const int lrow = lane & 15, lkh = lane >> 4;
    uint32_t lds0 = sA_u + a_phys(0, wM * 32 + lrow, lkh);
    uint32_t lds1 = sA_u + a_phys(0, wM * 32 + 16 + lrow, lkh);

    // ---- prologue: stage x(0) ----
    {
        const float* xp = x + ((size_t)(r0 + xrow) * SEQ + 0) * DIM + xkb;
        #pragma unroll
        for (int c2 = 0; c2 < 4; ++c2) {
            float4 v0 = *(const float4*)(xp + c2 * 8);
            float4 v1 = *(const float4*)(xp + c2 * 8 + 4);
            union { __half2 h; uint32_t u; } q0, q1, q2, q3;
            q0.h = __floats2half2_rn(v0.x, v0.y);
            q1.h = __floats2half2_rn(v0.z, v0.w);
            q2.h = __floats2half2_rn(v1.x, v1.y);
            q3.h = __floats2half2_rn(v1.z, v1.w);
            int k = xkb + c2 * 8;
            *(uint4*)(sA + a_phys(k >> 4, xrow, (k >> 3) & 1)) =
                make_uint4(q0.u, q1.u, q2.u, q3.u);
        }
    }

    // full group barrier once (hq0 zero + x(0) visible)
    {
        __syncthreads();
        if (tid == 0) {
            __threadfence();
            unsigned long long t = atomicAdd(bar_ctr, 1ULL) + 1ULL;
            unsigned long long target =
                ((t + (unsigned long long)NGRP - 1ULL) / NGRP) *
                (unsigned long long)NGRP;
            unsigned long long v;
            do {
                asm volatile("ld.acquire.gpu.u64 %0, [%1];"
                             : "=l"(v) : "l"(bar_ctr) : "memory");
            } while (v < target);
        }
        __syncthreads();
    }

    for (int s = 0; s < SEQ; ++s) {
        // -- load int8 h(s) rows (L1-bypass), stage into sQ
        const signed char* hqp = g_hq[s & 1];
        const uint4* hqsrc =
            (const uint4*)(hqp + (size_t)(r0 + xrow) * HID + qt * 64);
        uint4 hqr[4];
        #pragma unroll
        for (int c = 0; c < 4; ++c) hqr[c] = __ldcv(hqsrc + c);
        #pragma unroll
        for (int c = 0; c < 4; ++c)
            *(uint4*)(sQ + xrow * ROWP + qt * 64 + c * 16) = hqr[c];
        __syncthreads();

        // accumulators
        float acc[2][2][4];
        uint32_t hc[2][2][2];
        int idot[4][4];
        #pragma unroll
        for (int mb = 0; mb < 2; ++mb)
            #pragma unroll
            for (int nb = 0; nb < 2; ++nb) {
                #pragma unroll
                for (int k = 0; k < 4; ++k) acc[mb][nb][k] = 0.f;
                hc[mb][nb][0] = 0u; hc[mb][nb][1] = 0u;
            }
        #pragma unroll
        for (int rj = 0; rj < 4; ++rj)
            #pragma unroll
            for (int cj = 0; cj < 4; ++cj) idot[rj][cj] = 0;

        auto tensor_ks = [&](int ks) {
            uint32_t am0[4], am1[4];
            ldsm4(am0, lds0 + ks * 2048);
            ldsm4(am1, lds1 + ks * 2048);
            mma_f16acc(hc[0][0], am0, bfr[ks][0][0], bfr[ks][0][1]);
            mma_f16acc(hc[0][1], am0, bfr[ks][1][0], bfr[ks][1][1]);
            mma_f16acc(hc[1][0], am1, bfr[ks][0][0], bfr[ks][0][1]);
            mma_f16acc(hc[1][1], am1, bfr[ks][1][0], bfr[ks][1][1]);
        };
        auto quad_block = [&](int qb) {   // 16 h-dims: 8 LDS.128 + 64 dp4a
            uint4 av[4], wv[4];
            #pragma unroll
            for (int rj = 0; rj < 4; ++rj)
                av[rj] = *(const uint4*)(sQ + Rr[rj] * ROWP + qb * 16);
            #pragma unroll
            for (int cj = 0; cj < 4; ++cj)
                wv[cj] = *(const uint4*)(sW + cloc[cj] * ROWP + qb * 16);
            #pragma unroll
            for (int rj = 0; rj < 4; ++rj)
                #pragma unroll
                for (int cj = 0; cj < 4; ++cj) {
                    int d = idot[rj][cj];
                    d = __dp4a((int)av[rj].x, (int)wv[cj].x, d);
                    d = __dp4a((int)av[rj].y, (int)wv[cj].y, d);
                    d = __dp4a((int)av[rj].z, (int)wv[cj].z, d);
                    d = __dp4a((int)av[rj].w, (int)wv[cj].w, d);
                    idot[rj][cj] = d;
                }
        };

        // -- interleaved: 1 MMA k-step : 2 int8 quad-blocks (keeps MMA queue
        //    fed without backpressure while dp4a streams on the integer pipe)
        #pragma unroll
        for (int g = 0; g < 8; ++g) {
            tensor_ks(g);
            quad_block(2 * g);
            quad_block(2 * g + 1);
        }

        // -- merge: promote f16 x-部分 accs, add scaled int dots
        promote(acc[0][0], hc[0][0]); promote(acc[0][1], hc[0][1]);
        promote(acc[1][0], hc[1][0]); promote(acc[1][1], hc[1][1]);
        #pragma unroll
        for (int rj = 0; rj < 4; ++rj)
            #pragma unroll
            for (int cj = 0; cj < 4; ++cj)
                acc[rj >> 1][cj >> 1][((rj & 1) << 1) | (cj & 1)] +=
                    (float)idot[rj][cj] * scW[cj];

        // -- gate exchange (R8)
        float zif[2][4], zgo[2][4];
        #pragma unroll
        for (int nb = 0; nb < 2; ++nb)
            #pragma unroll
            for (int k = 0; k < 4; ++k) {
                float s0 = __shfl_xor_sync(0xffffffffu, acc[0][nb][k], 1);
                float s1 = __shfl_xor_sync(0xffffffffu, acc[1][nb][k], 1);
                zif[nb][k] = myOdd ? s1 : acc[0][nb][k];
                zgo[nb][k] = myOdd ? acc[1][nb][k] : s0;
            }

        // -- cell update; h(s+1) stored as int8 (and fp16 only at the end)
        signed char* hqn = g_hq[(s + 1) & 1];
        #pragma unroll
        for (int nb = 0; nb < 2; ++nb) {
            int j = j0 + wN * 4 + nb * 2 + (q >> 1);
            float i0 = sig_mufu(zif[nb][0] + bI[nb]);
            float f0 = sig_mufu(zif[nb][1] + bF[nb]);
            float g0 = tanh_mufu(zgo[nb][0] + bG[nb]);
            float o0 = sig_mufu(zgo[nb][1] + bO[nb]);
            float i1 = sig_mufu(zif[nb][2] + bI[nb]);
            float f1 = sig_mufu(zif[nb][3] + bF[nb]);
            float g1 = tanh_mufu(zgo[nb][2] + bG[nb]);
            float o1 = sig_mufu(zgo[nb][3] + bO[nb]);
            cst[nb * 2 + 0] = f0 * cst[nb * 2 + 0] + i0 * g0;
            cst[nb * 2 + 1] = f1 * cst[nb * 2 + 1] + i1 * g1;
            float h0 = o0 * tanh_mufu(cst[nb * 2 + 0]);
            float h1 = o1 * tanh_mufu(cst[nb * 2 + 1]);
            int q0 = max(-127, min(127, __float2int_rn(h0 * 127.0f)));
            int q1 = max(-127, min(127, __float2int_rn(h1 * 127.0f)));
            hqn[(size_t)(r0 + rA) * HID + j]     = (signed char)q0;
            hqn[(size_t)(r0 + rA + 8) * HID + j] = (signed char)q1;
            if (s == SEQ - 1) {
                g_hfin[(size_t)(r0 + rA) * HID + j]     = __float2half_rn(h0);
                g_hfin[(size_t)(r0 + rA + 8) * HID + j] = __float2half_rn(h1);
            }
        }

        // -- split barrier: arrive, stage x(s+1) in the window, wait
        __syncthreads();
        unsigned long long tick = 0;
        if (tid == 0) {
            asm volatile("atom.add.release.gpu.global.u64 %0, [%1], 1;"
                         : "=l"(tick) : "l"(bar_ctr) : "memory");
            tick += 1ULL;
        }
        if (s + 1 < SEQ) {
            const float* xp = x + ((size_t)(r0 + xrow) * SEQ + (s + 1)) * DIM + xkb;
            #pragma unroll
            for (int c2 = 0; c2 < 4; ++c2) {
                float4 v0 = *(const float4*)(xp + c2 * 8);
                float4 v1 = *(const float4*)(xp + c2 * 8 + 4);
                union { __half2 h; uint32_t u; } q0, q1, q2, q3;
                q0.h = __floats2half2_rn(v0.x, v0.y);
                q1.h = __floats2half2_rn(v0.z, v0.w);
                q2.h = __floats2half2_rn(v1.x, v1.y);
                q3.h = __floats2half2_rn(v1.z, v1.w);
                int k = xkb + c2 * 8;
                *(uint4*)(sA + a_phys(k >> 4, xrow, (k >> 3) & 1)) =
                    make_uint4(q0.u, q1.u, q2.u, q3.u);
            }
        }
        if (tid == 0) {
            unsigned long long target =
                ((tick + (unsigned long long)NGRP - 1ULL) / NGRP) *
                (unsigned long long)NGRP;
            unsigned long long v;
            do {
                asm volatile("ld.acquire.gpu.u64 %0, [%1];"
                             : "=l"(v) : "l"(bar_ctr) : "memory");
            } while (v < target);
        }
        __syncthreads();
    }

    // ---- classifier + softmax (rows group-local) ----
    if (warp < 4) {
        const int row = cta * 4 + warp;
        const __half* hf = g_hfin;
        float acc10[10];
        #pragma unroll
        for (int c = 0; c < 10; ++c) acc10[c] = 0.f;
        uint4 hv = __ldcv((const uint4*)(hf + (size_t)row * HID + lane * 8));
        const __half* hvh = (const __half*)&hv;
        #pragma unroll
        for (int u = 0; u < 8; ++u) {
            float h = __half2float(hvh[u]);
            const float* wd = Wd + (size_t)(lane * 8 + u) * 10;
            #pragma unroll
            for (int c = 0; c < 10; ++c) acc10[c] += h * wd[c];
        }
        #pragma unroll
        for (int off = 16; off > 0; off >>= 1) {
            #pragma unroll
            for (int c = 0; c < 10; ++c)
                acc10[c] += __shfl_down_sync(0xffffffffu, acc10[c], off);
        }
        if (lane == 0) {
            float m = -3.0e38f;
            #pragma unroll
            for (int c = 0; c < 10; ++c) { acc10[c] += bd[c]; m = fmaxf(m, acc10[c]); }
            float ssum = 0.f;
            #pragma unroll
            for (int c = 0; c < 10; ++c) { acc10[c] = __expf(acc10[c] - m); ssum += acc10[c]; }
            float inv = 1.0f / ssum;
            #pragma unroll
            for (int c = 0; c < 10; ++c) out[(size_t)row * 10 + c] = acc10[c] * inv;
        }
    }
}

extern "C" void kernel_launch(void* const* d_in, const int* in_sizes, int n_in,
                              void* d_out, int out_size) {
    const float* x  = (const float*)d_in[0];
    const float* Wx = (const float*)d_in[1];
    const float* Wh = (const float*)d_in[2];
    const float* b  = (const float*)d_in[3];
    const float* Wd = (const float*)d_in[4];
    const float* bd = (const float*)d_in[5];
    (void)in_sizes; (void)n_in; (void)out_size;
    cudaFuncSetAttribute(lstm_i8, cudaFuncAttributeMaxDynamicSharedMemorySize,
                         SMEM_TOTAL);
    lstm_i8<<<NCTA, NTHR, SMEM_TOTAL>>>(x, Wx, Wh, b, Wd, bd, (float*)d_out);
}